// round 4
// baseline (speedup 1.0000x reference)
#include <cuda_runtime.h>

// LocalVariation: out[b, k, y, x] = x[b,y,x] - xp[b, y+i, x+j]  (replicate pad, 5x5, skip center)
// Input : [16, 1, 512, 512] f32
// Output: [16, 24, 512, 512] f32
//
// Tile: 128 (x) by 4 (y) pixels per block, blockDim (32,4)=128 threads.
// Each thread computes 4 consecutive x pixels -> float4 stores for all 24 channels.

#define KSZ   5
#define PAD   2
#define H     512
#define W     512
#define B     16
#define NCH   24
#define TILE_X 128
#define TILE_Y 4
#define SM_W  (TILE_X + 2 * PAD)   // 132 valid cols
#define SM_STRIDE 136              // 16B-aligned row stride (136*4 = 544 bytes)
#define SM_H  (TILE_Y + 2 * PAD)   // 8 rows
#define SM_ELEMS (SM_H * SM_W)     // 1056

__global__ __launch_bounds__(128, 8)
void localvar_kernel(const float* __restrict__ in, float* __restrict__ out) {
    __shared__ float sm[SM_H * SM_STRIDE];

    const int b   = blockIdx.z;
    const int by0 = blockIdx.y * TILE_Y;   // global y of tile row 0 (center coords)
    const int bx0 = blockIdx.x * TILE_X;   // global x of tile col 0 (center coords)

    const int tid = threadIdx.y * 32 + threadIdx.x;
    const float* inb = in + b * (H * W);

    // ---- fill smem tile with replicate-clamped input ----
    // smem[r][c] corresponds to global (by0 + r - PAD, bx0 + c - PAD), clamped.
    // 1056 elements / 128 threads -> fixed 9 iterations, fully unrolled so the
    // 9 LDGs issue back-to-back (MLP) before any dependent use.
    #pragma unroll
    for (int it = 0; it < 9; it++) {
        int idx = tid + it * 128;
        if (idx < SM_ELEMS) {
            int r = idx / SM_W;
            int c = idx - r * SM_W;
            int gy = by0 + r - PAD;
            int gx = bx0 + c - PAD;
            gy = gy < 0 ? 0 : (gy > H - 1 ? H - 1 : gy);
            gx = gx < 0 ? 0 : (gx > W - 1 ? W - 1 : gx);
            sm[r * SM_STRIDE + c] = inb[gy * W + gx];
        }
    }
    __syncthreads();

    // ---- compute ----
    const int tx = threadIdx.x;       // 0..31
    const int ty = threadIdx.y;       // 0..3
    const int px = tx * 4;            // local x of first of 4 pixels

    // Load the 5 rows x 8 cols this thread needs, as float4 pairs (16B-aligned).
    float rowv[KSZ][8];
    #pragma unroll
    for (int i = 0; i < KSZ; i++) {
        const float4* p = (const float4*)&sm[(ty + i) * SM_STRIDE + px];
        float4 a = p[0];
        float4 c = p[1];
        rowv[i][0] = a.x; rowv[i][1] = a.y; rowv[i][2] = a.z; rowv[i][3] = a.w;
        rowv[i][4] = c.x; rowv[i][5] = c.y; rowv[i][6] = c.z; rowv[i][7] = c.w;
    }

    const float c0 = rowv[PAD][PAD + 0];
    const float c1 = rowv[PAD][PAD + 1];
    const float c2 = rowv[PAD][PAD + 2];
    const float c3 = rowv[PAD][PAD + 3];

    const int gy  = by0 + ty;
    const int gx0 = bx0 + px;
    // out index base: ((b*NCH + k)*H + gy)*W + gx0
    float* outp = out + ((long long)b * NCH * H + gy) * W + gx0;

    int k = 0;
    #pragma unroll
    for (int i = 0; i < KSZ; i++) {
        #pragma unroll
        for (int j = 0; j < KSZ; j++) {
            if (i == PAD && j == PAD) continue;
            float4 v;
            v.x = c0 - rowv[i][j + 0];
            v.y = c1 - rowv[i][j + 1];
            v.z = c2 - rowv[i][j + 2];
            v.w = c3 - rowv[i][j + 3];
            *(float4*)(outp + (long long)k * (H * W)) = v;
            k++;
        }
    }
}

extern "C" void kernel_launch(void* const* d_in, const int* in_sizes, int n_in,
                              void* d_out, int out_size) {
    const float* x = (const float*)d_in[0];
    float* out = (float*)d_out;
    dim3 block(32, 4, 1);
    dim3 grid(W / TILE_X, H / TILE_Y, B);
    localvar_kernel<<<grid, block>>>(x, out);
}

// round 7
// speedup vs baseline: 1.1338x; 1.1338x over previous
#include <cuda_runtime.h>

// LocalVariation: out[b, k, y, x] = x[b,y,x] - xp[b, y+i, x+j]  (replicate pad, 5x5, skip center)
// Input : [16, 1, 512, 512] f32
// Output: [16, 24, 512, 512] f32
//
// Tile: 128 (x) by 4 (y) pixels per block, blockDim (32,4)=128 threads.
// Each thread computes 4 consecutive x pixels -> float4 streaming stores, 24 channels.
// Rows are re-read from smem per channel row (no register row-cache) to keep
// register count low -> 12 blocks/SM (75% occupancy ceiling).

#define KSZ   5
#define PAD   2
#define H     512
#define W     512
#define B     16
#define NCH   24
#define TILE_X 128
#define TILE_Y 4
#define SM_W  (TILE_X + 2 * PAD)   // 132 valid cols
#define SM_STRIDE 136              // 16B-aligned row stride
#define SM_H  (TILE_Y + 2 * PAD)   // 8 rows
#define SM_ELEMS (SM_H * SM_W)     // 1056

__global__ __launch_bounds__(128, 12)
void localvar_kernel(const float* __restrict__ in, float* __restrict__ out) {
    __shared__ float sm[SM_H * SM_STRIDE];

    const int b   = blockIdx.z;
    const int by0 = blockIdx.y * TILE_Y;
    const int bx0 = blockIdx.x * TILE_X;

    const int tid = threadIdx.y * 32 + threadIdx.x;
    const float* inb = in + b * (H * W);

    // ---- fill smem tile with replicate-clamped input ----
    #pragma unroll
    for (int it = 0; it < 9; it++) {
        int idx = tid + it * 128;
        if (idx < SM_ELEMS) {
            int r = idx / SM_W;
            int c = idx - r * SM_W;
            int gy = by0 + r - PAD;
            int gx = bx0 + c - PAD;
            gy = gy < 0 ? 0 : (gy > H - 1 ? H - 1 : gy);
            gx = gx < 0 ? 0 : (gx > W - 1 ? W - 1 : gx);
            sm[r * SM_STRIDE + c] = inb[gy * W + gx];
        }
    }
    __syncthreads();

    // ---- compute ----
    const int tx = threadIdx.x;       // 0..31
    const int ty = threadIdx.y;       // 0..3
    const int px = tx * 4;            // local x of first of 4 pixels

    // Center pixels: sm[ty+PAD][px+PAD .. px+PAD+3], 8B-aligned -> two LDS.64
    const float2 cA = *(const float2*)&sm[(ty + PAD) * SM_STRIDE + px + 2];
    const float2 cB = *(const float2*)&sm[(ty + PAD) * SM_STRIDE + px + 4];
    const float c0 = cA.x, c1 = cA.y, c2 = cB.x, c3 = cB.y;

    const int gy  = by0 + ty;
    const int gx0 = bx0 + px;
    float* outp = out + ((long long)b * NCH * H + gy) * W + gx0;

    int k = 0;
    #pragma unroll
    for (int i = 0; i < KSZ; i++) {
        // Load this row's 8 floats (16B-aligned pair of LDS.128)
        const float4* p = (const float4*)&sm[(ty + i) * SM_STRIDE + px];
        float4 a = p[0];
        float4 d = p[1];
        float rr[8] = {a.x, a.y, a.z, a.w, d.x, d.y, d.z, d.w};

        #pragma unroll
        for (int j = 0; j < KSZ; j++) {
            if (i == PAD && j == PAD) continue;
            float4 v;
            v.x = c0 - rr[j + 0];
            v.y = c1 - rr[j + 1];
            v.z = c2 - rr[j + 2];
            v.w = c3 - rr[j + 3];
            __stcs((float4*)(outp + (long long)k * (H * W)), v);
            k++;
        }
    }
}

extern "C" void kernel_launch(void* const* d_in, const int* in_sizes, int n_in,
                              void* d_out, int out_size) {
    const float* x = (const float*)d_in[0];
    float* out = (float*)d_out;
    dim3 block(32, 4, 1);
    dim3 grid(W / TILE_X, H / TILE_Y, B);
    localvar_kernel<<<grid, block>>>(x, out);
}